// round 12
// baseline (speedup 1.0000x reference)
#include <cuda_runtime.h>
#include <math.h>

#define GAMMA 0.99f
#define LAM   0.95f
#define GL    (GAMMA * LAM)
#define EPSN  1e-8

#define CHUNKS 64
#define MAXN   8192
#define TPB    256
#define TPBS   64                        // scan block size -> 128 blocks
#define NSLOT  (CHUNKS * MAXN)
#define RBLK   (NSLOT / TPB)             // 2048 stats partial slots

// Static device scratch (no allocations). Zero-initialized.
__device__ float2   g_CD[NSLOT];         // {C, D}               4 MB
__device__ float4   g_S[NSLOT];          // {S1, SC, S2, SDC}   16 MB
__device__ float    g_SC2[NSLOT];        //                      4 MB
__device__ float    g_carry[NSLOT];      //                      2 MB
__device__ double   g_part[2 * RBLK];
__device__ unsigned g_ctr;               // last-block counter (self-resetting)
__device__ float    g_mean;
__device__ float    g_inv;               // 1 / (std + eps)

// ---------------------------------------------------------------------------
// Phase 1: per (chunk, 4-col) thread, compose the reverse recurrence into
// a_out = D + C*a_in + sufficient statistics. Inner loop identical to the
// measured-38.5us version; only the scratch layout is slimmer (24 MB).
// ---------------------------------------------------------------------------
__global__ __launch_bounds__(TPB)
void gae_phase1(const float* __restrict__ rw, const float* __restrict__ val,
                const int* __restrict__ dn, int N, int L) {
    int groups = N >> 2;
    int tid = blockIdx.x * blockDim.x + threadIdx.x;
    if (tid >= CHUNKS * groups) return;
    int c   = tid / groups;
    int g   = tid - c * groups;
    int col = g << 2;
    int t0  = c * L;
    int t1  = t0 + L - 1;

    float C[4]  = {1.f, 1.f, 1.f, 1.f};
    float D[4]  = {0.f, 0.f, 0.f, 0.f};
    float S1[4] = {0.f, 0.f, 0.f, 0.f};
    float SC[4] = {0.f, 0.f, 0.f, 0.f};
    float S2[4] = {0.f, 0.f, 0.f, 0.f};
    float SDC[4]= {0.f, 0.f, 0.f, 0.f};
    float SC2[4]= {0.f, 0.f, 0.f, 0.f};

    float4 vn = *reinterpret_cast<const float4*>(val + (size_t)(t1 + 1) * N + col);
    #pragma unroll 4
    for (int t = t1; t >= t0; --t) {
        float4 r  = *reinterpret_cast<const float4*>(rw + (size_t)t * N + col);
        int4   dd = *reinterpret_cast<const int4*>(dn + (size_t)t * N + col);
        float4 vc = *reinterpret_cast<const float4*>(val + (size_t)t * N + col);

        float rr[4] = {r.x, r.y, r.z, r.w};
        float vv[4] = {vc.x, vc.y, vc.z, vc.w};
        float vnn[4]= {vn.x, vn.y, vn.z, vn.w};
        int   di[4] = {dd.x, dd.y, dd.z, dd.w};

        #pragma unroll
        for (int j = 0; j < 4; ++j) {
            float nt  = di[j] ? 0.f : 1.f;
            float del = fmaf(GAMMA * nt, vnn[j], rr[j]) - vv[j];
            float cf  = GL * nt;
            D[j] = fmaf(cf, D[j], del);
            C[j] *= cf;
            S1[j] += D[j];
            SC[j] += C[j];
            S2[j]  = fmaf(D[j], D[j], S2[j]);
            SDC[j] = fmaf(D[j], C[j], SDC[j]);
            SC2[j] = fmaf(C[j], C[j], SC2[j]);
        }
        vn = vc;
    }
    size_t o = (size_t)c * N + col;
    #pragma unroll
    for (int j = 0; j < 4; ++j) {
        g_CD [o + j] = make_float2(C[j], D[j]);
        g_S  [o + j] = make_float4(S1[j], SC[j], S2[j], SDC[j]);
        g_SC2[o + j] = SC2[j];
    }
}

// ---------------------------------------------------------------------------
// Scan: one thread per column, reverse-scan ONLY {C,D} (4 MB total) to produce
// the carry entering each chunk. TPB=64 -> 128 blocks so it spreads across
// most SMs; unroll-8 batches the loads.
// ---------------------------------------------------------------------------
__global__ __launch_bounds__(TPBS)
void gae_scan(int N) {
    int col = blockIdx.x * blockDim.x + threadIdx.x;
    if (col >= N) return;
    float a = 0.f;
    #pragma unroll 8
    for (int c = CHUNKS - 1; c >= 0; --c) {
        size_t o = (size_t)c * N + col;
        g_carry[o] = a;
        float2 cd = g_CD[o];
        a = fmaf(cd.x, a, cd.y);
    }
}

// ---------------------------------------------------------------------------
// Stats (+fused finalize): one thread per (chunk, column) — 2048 blocks,
// full-BW read of the 22 MB of stats+carries. Closed forms:
//   sum_chunk   = S1 + SC*a ;  sumsq_chunk = S2 + 2*SDC*a + SC2*a*a
// Last-arriving block reduces the partials in fixed order -> mean, inv.
// Non-last blocks exit immediately (no release wait; next kernel consumes).
// ---------------------------------------------------------------------------
__global__ __launch_bounds__(TPB)
void gae_stats(int total, long long M) {
    const unsigned nb = gridDim.x;
    int i = blockIdx.x * blockDim.x + threadIdx.x;
    float ts = 0.f, ts2 = 0.f;
    if (i < total) {
        float4 S   = g_S[i];
        float  sc2 = g_SC2[i];
        float  a   = g_carry[i];
        ts  = fmaf(S.y, a, S.x);
        ts2 = fmaf(fmaf(sc2, a, 2.f * S.w), a, S.z);
    }
    __shared__ double ss[TPB];
    __shared__ double ss2[TPB];
    ss[threadIdx.x]  = (double)ts;
    ss2[threadIdx.x] = (double)ts2;
    __syncthreads();
    for (int st = TPB / 2; st > 0; st >>= 1) {
        if (threadIdx.x < st) {
            ss[threadIdx.x]  += ss[threadIdx.x + st];
            ss2[threadIdx.x] += ss2[threadIdx.x + st];
        }
        __syncthreads();
    }
    __shared__ bool s_last;
    if (threadIdx.x == 0) {
        g_part[2 * blockIdx.x]     = ss[0];
        g_part[2 * blockIdx.x + 1] = ss2[0];
        __threadfence();
        unsigned old = atomicAdd(&g_ctr, 1u);
        s_last = (old == nb - 1u);
    }
    __syncthreads();
    if (!s_last) return;

    double s = 0.0, s2 = 0.0;
    for (int k = threadIdx.x; k < (int)nb; k += TPB) {
        s  += g_part[2 * k];
        s2 += g_part[2 * k + 1];
    }
    ss[threadIdx.x]  = s;
    ss2[threadIdx.x] = s2;
    __syncthreads();
    for (int st = TPB / 2; st > 0; st >>= 1) {
        if (threadIdx.x < st) {
            ss[threadIdx.x]  += ss[threadIdx.x + st];
            ss2[threadIdx.x] += ss2[threadIdx.x + st];
        }
        __syncthreads();
    }
    if (threadIdx.x == 0) {
        double mean = ss[0] / (double)M;
        double var  = (ss2[0] - ss[0] * ss[0] / (double)M) / (double)(M - 1);
        if (var < 0.0) var = 0.0;
        g_mean = (float)mean;
        g_inv  = (float)(1.0 / (sqrt(var) + EPSN));
        g_ctr  = 0u;   // reset for next graph replay
    }
}

// ---------------------------------------------------------------------------
// Write pass: untouched, measured 50.4us / ~6.5 TB/s.
// ---------------------------------------------------------------------------
__global__ __launch_bounds__(TPB)
void gae_write(const float* __restrict__ rw, const float* __restrict__ val,
               const int* __restrict__ dn, float* __restrict__ adv,
               float* __restrict__ ret, int N, int L) {
    int groups = N >> 2;
    int tid = blockIdx.x * blockDim.x + threadIdx.x;
    if (tid >= CHUNKS * groups) return;
    int c   = tid / groups;
    int g   = tid - c * groups;
    int col = g << 2;
    int t0  = c * L;
    int t1  = t0 + L - 1;

    float m   = g_mean;
    float inv = g_inv;

    float4 a  = *reinterpret_cast<const float4*>(g_carry + (size_t)c * N + col);
    float4 vn = *reinterpret_cast<const float4*>(val + (size_t)(t1 + 1) * N + col);

    #pragma unroll 4
    for (int t = t1; t >= t0; --t) {
        float4 r  = *reinterpret_cast<const float4*>(rw + (size_t)t * N + col);
        int4   dd = *reinterpret_cast<const int4*>(dn + (size_t)t * N + col);
        float4 vc = *reinterpret_cast<const float4*>(val + (size_t)t * N + col);

        float nt, del;
        nt = dd.x ? 0.f : 1.f; del = fmaf(GAMMA * nt, vn.x, r.x) - vc.x;
        a.x = fmaf(GL * nt, a.x, del);
        nt = dd.y ? 0.f : 1.f; del = fmaf(GAMMA * nt, vn.y, r.y) - vc.y;
        a.y = fmaf(GL * nt, a.y, del);
        nt = dd.z ? 0.f : 1.f; del = fmaf(GAMMA * nt, vn.z, r.z) - vc.z;
        a.z = fmaf(GL * nt, a.z, del);
        nt = dd.w ? 0.f : 1.f; del = fmaf(GAMMA * nt, vn.w, r.w) - vc.w;
        a.w = fmaf(GL * nt, a.w, del);

        size_t o = (size_t)t * N + col;
        *reinterpret_cast<float4*>(adv + o) =
            make_float4((a.x - m) * inv, (a.y - m) * inv,
                        (a.z - m) * inv, (a.w - m) * inv);
        *reinterpret_cast<float4*>(ret + o) =
            make_float4(a.x + vc.x, a.y + vc.y, a.z + vc.z, a.w + vc.w);

        vn = vc;
    }
}

extern "C" void kernel_launch(void* const* d_in, const int* in_sizes, int n_in,
                              void* d_out, int out_size) {
    const float* rw  = (const float*)d_in[0];   // rewards [T, N]
    const float* val = (const float*)d_in[1];   // values  [T+1, N]
    const int*   dn  = (const int*)d_in[2];     // dones   [T, N]
    float* out = (float*)d_out;                 // [adv_norm TN | returns TN]

    int TN = in_sizes[0];
    int N  = in_sizes[1] - in_sizes[0];
    int T  = TN / N;
    int L  = T / CHUNKS;

    int groups  = N >> 2;
    int blocks1 = (CHUNKS * groups + TPB - 1) / TPB;   // 512
    int total   = CHUNKS * N;
    int blocksS = (total + TPB - 1) / TPB;             // 2048

    float* adv = out;
    float* ret = out + (size_t)TN;

    gae_phase1<<<blocks1, TPB>>>(rw, val, dn, N, L);
    gae_scan<<<(N + TPBS - 1) / TPBS, TPBS>>>(N);
    gae_stats<<<blocksS, TPB>>>(total, (long long)TN);
    gae_write<<<blocks1, TPB>>>(rw, val, dn, adv, ret, N, L);
}

// round 13
// speedup vs baseline: 1.0420x; 1.0420x over previous
#include <cuda_runtime.h>
#include <math.h>

#define GAMMA 0.99f
#define LAM   0.95f
#define GL    (GAMMA * LAM)
#define EPSN  1e-8

#define CHUNKS 64
#define MAXN   8192
#define TPB    256
#define NSLOT  (CHUNKS * MAXN)
#define MAXSCANB (MAXN / TPB)   // 32 scanner blocks

// Static device scratch (no allocations). Zero-initialized.
__device__ float4   g_P[NSLOT];          // {C, D, S1, SC}    8 MB
__device__ float4   g_Q[NSLOT];          // {S2, SDC, SC2,_}  8 MB
__device__ float    g_carry[NSLOT];      //                   2 MB
__device__ double   g_part[2 * MAXSCANB];
__device__ unsigned g_c0, g_c1;          // counters (reset by final block)
__device__ float    g_mean;
__device__ float    g_inv;               // 1 / (std + eps)

__device__ __forceinline__ unsigned vld(const unsigned* p) {
    return *(const volatile unsigned*)p;
}

// ---------------------------------------------------------------------------
// K1 = proven phase1 (two-float4 store layout, measured 38.5us) + cheap tail:
//   every block: arrive on g_c0, then blocks >= scanB EXIT (no spinning).
//   blocks 0..scanB-1: spin until all arrived (cost = finish skew only),
//   then run the phase2 body: one column per thread (col = blk*256+tid,
//   coalesced float4 reads of g_P/g_Q), reverse-scan chunk summaries ->
//   carries + closed-form sum/sumsq; block reduce (double) -> fixed partial
//   slot; LAST scanner block reduces slots in fixed order -> mean, inv;
//   resets counters. Deterministic: assignments & reduce order all fixed.
// ---------------------------------------------------------------------------
__global__ __launch_bounds__(TPB)
void gae_k1(const float* __restrict__ rw, const float* __restrict__ val,
            const int* __restrict__ dn, int N, int L, long long M) {
    const int groups = N >> 2;
    const int total  = CHUNKS * groups;
    const unsigned nb = gridDim.x;
    const int scanB  = N / TPB;
    const int tid = blockIdx.x * TPB + threadIdx.x;

    // ---- phase1 body (verbatim R2) ----
    if (tid < total) {
        int c   = tid / groups;
        int g   = tid - c * groups;
        int col = g << 2;
        int t0  = c * L;
        int t1  = t0 + L - 1;

        float C[4]  = {1.f, 1.f, 1.f, 1.f};
        float D[4]  = {0.f, 0.f, 0.f, 0.f};
        float S1[4] = {0.f, 0.f, 0.f, 0.f};
        float SC[4] = {0.f, 0.f, 0.f, 0.f};
        float S2[4] = {0.f, 0.f, 0.f, 0.f};
        float SDC[4]= {0.f, 0.f, 0.f, 0.f};
        float SC2[4]= {0.f, 0.f, 0.f, 0.f};

        float4 vn = *reinterpret_cast<const float4*>(val + (size_t)(t1 + 1) * N + col);
        #pragma unroll 4
        for (int t = t1; t >= t0; --t) {
            float4 r  = *reinterpret_cast<const float4*>(rw + (size_t)t * N + col);
            int4   dd = *reinterpret_cast<const int4*>(dn + (size_t)t * N + col);
            float4 vc = *reinterpret_cast<const float4*>(val + (size_t)t * N + col);

            float rr[4] = {r.x, r.y, r.z, r.w};
            float vv[4] = {vc.x, vc.y, vc.z, vc.w};
            float vnn[4]= {vn.x, vn.y, vn.z, vn.w};
            int   di[4] = {dd.x, dd.y, dd.z, dd.w};

            #pragma unroll
            for (int j = 0; j < 4; ++j) {
                float nt  = di[j] ? 0.f : 1.f;
                float del = fmaf(GAMMA * nt, vnn[j], rr[j]) - vv[j];
                float cf  = GL * nt;
                D[j] = fmaf(cf, D[j], del);
                C[j] *= cf;
                S1[j] += D[j];
                SC[j] += C[j];
                S2[j]  = fmaf(D[j], D[j], S2[j]);
                SDC[j] = fmaf(D[j], C[j], SDC[j]);
                SC2[j] = fmaf(C[j], C[j], SC2[j]);
            }
            vn = vc;
        }
        size_t o = (size_t)c * N + col;
        #pragma unroll
        for (int j = 0; j < 4; ++j) {
            g_P[o + j] = make_float4(C[j], D[j], S1[j], SC[j]);
            g_Q[o + j] = make_float4(S2[j], SDC[j], SC2[j], 0.f);
        }
    }

    // ---- arrival; non-scanner blocks exit immediately ----
    __threadfence();
    __syncthreads();
    if (threadIdx.x == 0) atomicAdd(&g_c0, 1u);
    if ((int)blockIdx.x >= scanB) return;

    if (threadIdx.x == 0) {
        while (vld(&g_c0) < nb) __nanosleep(128);
        __threadfence();
    }
    __syncthreads();

    // ---- phase2 body: one column per thread, coalesced ----
    float ts = 0.f, ts2 = 0.f;
    {
        int col = blockIdx.x * TPB + threadIdx.x;
        float a = 0.f;
        #pragma unroll 8
        for (int cc = CHUNKS - 1; cc >= 0; --cc) {
            size_t o = (size_t)cc * N + col;
            g_carry[o] = a;
            float4 P = g_P[o];
            float4 Q = g_Q[o];
            ts  += fmaf(P.w, a, P.z);
            ts2 += fmaf(fmaf(Q.z, a, 2.f * Q.y), a, Q.x);
            a = fmaf(P.x, a, P.y);
        }
    }

    __shared__ double ss[TPB];
    __shared__ double ss2[TPB];
    ss[threadIdx.x]  = (double)ts;
    ss2[threadIdx.x] = (double)ts2;
    __syncthreads();
    for (int st = TPB / 2; st > 0; st >>= 1) {
        if (threadIdx.x < st) {
            ss[threadIdx.x]  += ss[threadIdx.x + st];
            ss2[threadIdx.x] += ss2[threadIdx.x + st];
        }
        __syncthreads();
    }

    __shared__ bool s_last;
    if (threadIdx.x == 0) {
        g_part[2 * blockIdx.x]     = ss[0];
        g_part[2 * blockIdx.x + 1] = ss2[0];
        __threadfence();
        unsigned old = atomicAdd(&g_c1, 1u);
        s_last = (old == (unsigned)scanB - 1u);
    }
    __syncthreads();
    if (!s_last) return;

    // ---- final reduce (fixed order over scanB slots) ----
    if (threadIdx.x == 0) {
        double s = 0.0, s2 = 0.0;
        for (int i = 0; i < scanB; ++i) {
            s  += g_part[2 * i];
            s2 += g_part[2 * i + 1];
        }
        double mean = s / (double)M;
        double var  = (s2 - s * s / (double)M) / (double)(M - 1);
        if (var < 0.0) var = 0.0;
        g_mean = (float)mean;
        g_inv  = (float)(1.0 / (sqrt(var) + EPSN));
        g_c0 = 0u;  g_c1 = 0u;             // safe: all blocks passed/exited
        __threadfence();
    }
}

// ---------------------------------------------------------------------------
// K2: proven write pass (untouched ~50us / ~6 TB/s idiom).
// ---------------------------------------------------------------------------
__global__ __launch_bounds__(TPB)
void gae_write(const float* __restrict__ rw, const float* __restrict__ val,
               const int* __restrict__ dn, float* __restrict__ adv,
               float* __restrict__ ret, int N, int L) {
    int groups = N >> 2;
    int tid = blockIdx.x * blockDim.x + threadIdx.x;
    if (tid >= CHUNKS * groups) return;
    int c   = tid / groups;
    int g   = tid - c * groups;
    int col = g << 2;
    int t0  = c * L;
    int t1  = t0 + L - 1;

    float m   = g_mean;
    float inv = g_inv;

    float4 a  = *reinterpret_cast<const float4*>(g_carry + (size_t)c * N + col);
    float4 vn = *reinterpret_cast<const float4*>(val + (size_t)(t1 + 1) * N + col);

    #pragma unroll 4
    for (int t = t1; t >= t0; --t) {
        float4 r  = *reinterpret_cast<const float4*>(rw + (size_t)t * N + col);
        int4   dd = *reinterpret_cast<const int4*>(dn + (size_t)t * N + col);
        float4 vc = *reinterpret_cast<const float4*>(val + (size_t)t * N + col);

        float nt, del;
        nt = dd.x ? 0.f : 1.f; del = fmaf(GAMMA * nt, vn.x, r.x) - vc.x;
        a.x = fmaf(GL * nt, a.x, del);
        nt = dd.y ? 0.f : 1.f; del = fmaf(GAMMA * nt, vn.y, r.y) - vc.y;
        a.y = fmaf(GL * nt, a.y, del);
        nt = dd.z ? 0.f : 1.f; del = fmaf(GAMMA * nt, vn.z, r.z) - vc.z;
        a.z = fmaf(GL * nt, a.z, del);
        nt = dd.w ? 0.f : 1.f; del = fmaf(GAMMA * nt, vn.w, r.w) - vc.w;
        a.w = fmaf(GL * nt, a.w, del);

        size_t o = (size_t)t * N + col;
        *reinterpret_cast<float4*>(adv + o) =
            make_float4((a.x - m) * inv, (a.y - m) * inv,
                        (a.z - m) * inv, (a.w - m) * inv);
        *reinterpret_cast<float4*>(ret + o) =
            make_float4(a.x + vc.x, a.y + vc.y, a.z + vc.z, a.w + vc.w);

        vn = vc;
    }
}

extern "C" void kernel_launch(void* const* d_in, const int* in_sizes, int n_in,
                              void* d_out, int out_size) {
    const float* rw  = (const float*)d_in[0];   // rewards [T, N]
    const float* val = (const float*)d_in[1];   // values  [T+1, N]
    const int*   dn  = (const int*)d_in[2];     // dones   [T, N]
    float* out = (float*)d_out;                 // [adv_norm TN | returns TN]

    int TN = in_sizes[0];
    int N  = in_sizes[1] - in_sizes[0];
    int T  = TN / N;
    int L  = T / CHUNKS;

    int groups = N >> 2;
    int blocks = (CHUNKS * groups + TPB - 1) / TPB;   // 512: single wave

    float* adv = out;
    float* ret = out + (size_t)TN;

    gae_k1<<<blocks, TPB>>>(rw, val, dn, N, L, (long long)TN);
    gae_write<<<blocks, TPB>>>(rw, val, dn, adv, ret, N, L);
}

// round 14
// speedup vs baseline: 1.1489x; 1.1025x over previous
#include <cuda_runtime.h>
#include <math.h>

#define GAMMA 0.99f
#define LAM   0.95f
#define GL    (GAMMA * LAM)
#define EPSN  1e-8

#define CHUNKS 64
#define MAXN   8192
#define TPB    256
#define P2BLK  (MAXN / TPB)   // 32 partial slots

// Static device scratch (no allocations). Zero-initialized.
__device__ float4   g_P[CHUNKS * MAXN];   // {C, D, S1, SC}    8 MB
__device__ float4   g_Q[CHUNKS * MAXN];   // {S2, SDC, SC2,_}  8 MB
__device__ float    g_carry[CHUNKS * MAXN];
__device__ double   g_part[2 * P2BLK];
__device__ unsigned g_ctr;                // last-block counter (self-resets)
__device__ float    g_mean;
__device__ float    g_inv;                // 1 / (std + eps)

// ---------------------------------------------------------------------------
// Phase 1: per (chunk, 4-column group), compose the reverse recurrence into
// a_out = D + C * a_in and accumulate sufficient statistics. Identical to the
// measured-38.5us kernel except unroll 4 -> 8 (more load-batch MLP).
// ---------------------------------------------------------------------------
__global__ __launch_bounds__(TPB)
void gae_phase1(const float* __restrict__ rw, const float* __restrict__ val,
                const int* __restrict__ dn, int N, int L) {
    int groups = N >> 2;
    int tid = blockIdx.x * blockDim.x + threadIdx.x;
    if (tid >= CHUNKS * groups) return;
    int c   = tid / groups;
    int g   = tid - c * groups;
    int col = g << 2;
    int t0  = c * L;
    int t1  = t0 + L - 1;

    float C[4]  = {1.f, 1.f, 1.f, 1.f};
    float D[4]  = {0.f, 0.f, 0.f, 0.f};
    float S1[4] = {0.f, 0.f, 0.f, 0.f};
    float SC[4] = {0.f, 0.f, 0.f, 0.f};
    float S2[4] = {0.f, 0.f, 0.f, 0.f};
    float SDC[4]= {0.f, 0.f, 0.f, 0.f};
    float SC2[4]= {0.f, 0.f, 0.f, 0.f};

    float4 vn = *reinterpret_cast<const float4*>(val + (size_t)(t1 + 1) * N + col);
    #pragma unroll 8
    for (int t = t1; t >= t0; --t) {
        float4 r  = *reinterpret_cast<const float4*>(rw + (size_t)t * N + col);
        int4   dd = *reinterpret_cast<const int4*>(dn + (size_t)t * N + col);
        float4 vc = *reinterpret_cast<const float4*>(val + (size_t)t * N + col);

        float rr[4] = {r.x, r.y, r.z, r.w};
        float vv[4] = {vc.x, vc.y, vc.z, vc.w};
        float vnn[4]= {vn.x, vn.y, vn.z, vn.w};
        int   di[4] = {dd.x, dd.y, dd.z, dd.w};

        #pragma unroll
        for (int j = 0; j < 4; ++j) {
            float nt  = di[j] ? 0.f : 1.f;
            float del = fmaf(GAMMA * nt, vnn[j], rr[j]) - vv[j];
            float cf  = GL * nt;
            D[j] = fmaf(cf, D[j], del);
            C[j] *= cf;
            S1[j] += D[j];
            SC[j] += C[j];
            S2[j]  = fmaf(D[j], D[j], S2[j]);
            SDC[j] = fmaf(D[j], C[j], SDC[j]);
            SC2[j] = fmaf(C[j], C[j], SC2[j]);
        }
        vn = vc;
    }
    size_t o = (size_t)c * N + col;
    #pragma unroll
    for (int j = 0; j < 4; ++j) {
        g_P[o + j] = make_float4(C[j], D[j], S1[j], SC[j]);
        g_Q[o + j] = make_float4(S2[j], SDC[j], SC2[j], 0.f);
    }
}

// ---------------------------------------------------------------------------
// Phase 2 (+fused finalize): R2's phase2 body verbatim (one thread/column,
// TPB=256, 32 blocks), then last-arriving block reduces the 32 partials in
// fixed order -> mean, 1/(std+eps), ddof=1. Non-last blocks exit (no wait;
// the write kernel consumes the result after the graph edge).
// ---------------------------------------------------------------------------
__global__ __launch_bounds__(TPB)
void gae_phase2(int N, long long M) {
    const unsigned nb = gridDim.x;
    int col = blockIdx.x * blockDim.x + threadIdx.x;
    float ts = 0.f, ts2 = 0.f;
    if (col < N) {
        float a = 0.f;
        #pragma unroll 8
        for (int c = CHUNKS - 1; c >= 0; --c) {
            size_t o = (size_t)c * N + col;
            g_carry[o] = a;
            float4 P = g_P[o];
            float4 Q = g_Q[o];
            ts  += fmaf(P.w, a, P.z);
            ts2 += fmaf(fmaf(Q.z, a, 2.f * Q.y), a, Q.x);
            a = fmaf(P.x, a, P.y);
        }
    }
    __shared__ double ss[TPB];
    __shared__ double ss2[TPB];
    ss[threadIdx.x]  = (double)ts;
    ss2[threadIdx.x] = (double)ts2;
    __syncthreads();
    for (int st = TPB / 2; st > 0; st >>= 1) {
        if (threadIdx.x < st) {
            ss[threadIdx.x]  += ss[threadIdx.x + st];
            ss2[threadIdx.x] += ss2[threadIdx.x + st];
        }
        __syncthreads();
    }
    __shared__ bool s_last;
    if (threadIdx.x == 0) {
        g_part[2 * blockIdx.x]     = ss[0];
        g_part[2 * blockIdx.x + 1] = ss2[0];
        __threadfence();
        unsigned old = atomicAdd(&g_ctr, 1u);
        s_last = (old == nb - 1u);
    }
    __syncthreads();
    if (!s_last) return;

    if (threadIdx.x == 0) {
        double s = 0.0, s2 = 0.0;
        for (int i = 0; i < (int)nb; ++i) {       // fixed order, deterministic
            s  += g_part[2 * i];
            s2 += g_part[2 * i + 1];
        }
        double mean = s / (double)M;
        double var  = (s2 - s * s / (double)M) / (double)(M - 1);
        if (var < 0.0) var = 0.0;
        g_mean = (float)mean;
        g_inv  = (float)(1.0 / (sqrt(var) + EPSN));
        g_ctr  = 0u;                              // reset for next graph replay
        __threadfence();
    }
}

// ---------------------------------------------------------------------------
// Write pass: untouched (measured ~50us / 75% DRAM).
// ---------------------------------------------------------------------------
__global__ __launch_bounds__(TPB)
void gae_write(const float* __restrict__ rw, const float* __restrict__ val,
               const int* __restrict__ dn, float* __restrict__ adv,
               float* __restrict__ ret, int N, int L) {
    int groups = N >> 2;
    int tid = blockIdx.x * blockDim.x + threadIdx.x;
    if (tid >= CHUNKS * groups) return;
    int c   = tid / groups;
    int g   = tid - c * groups;
    int col = g << 2;
    int t0  = c * L;
    int t1  = t0 + L - 1;

    float m   = g_mean;
    float inv = g_inv;

    float4 a  = *reinterpret_cast<const float4*>(g_carry + (size_t)c * N + col);
    float4 vn = *reinterpret_cast<const float4*>(val + (size_t)(t1 + 1) * N + col);

    #pragma unroll 4
    for (int t = t1; t >= t0; --t) {
        float4 r  = *reinterpret_cast<const float4*>(rw + (size_t)t * N + col);
        int4   dd = *reinterpret_cast<const int4*>(dn + (size_t)t * N + col);
        float4 vc = *reinterpret_cast<const float4*>(val + (size_t)t * N + col);

        float nt, del;
        nt = dd.x ? 0.f : 1.f; del = fmaf(GAMMA * nt, vn.x, r.x) - vc.x;
        a.x = fmaf(GL * nt, a.x, del);
        nt = dd.y ? 0.f : 1.f; del = fmaf(GAMMA * nt, vn.y, r.y) - vc.y;
        a.y = fmaf(GL * nt, a.y, del);
        nt = dd.z ? 0.f : 1.f; del = fmaf(GAMMA * nt, vn.z, r.z) - vc.z;
        a.z = fmaf(GL * nt, a.z, del);
        nt = dd.w ? 0.f : 1.f; del = fmaf(GAMMA * nt, vn.w, r.w) - vc.w;
        a.w = fmaf(GL * nt, a.w, del);

        size_t o = (size_t)t * N + col;
        *reinterpret_cast<float4*>(adv + o) =
            make_float4((a.x - m) * inv, (a.y - m) * inv,
                        (a.z - m) * inv, (a.w - m) * inv);
        *reinterpret_cast<float4*>(ret + o) =
            make_float4(a.x + vc.x, a.y + vc.y, a.z + vc.z, a.w + vc.w);

        vn = vc;
    }
}

extern "C" void kernel_launch(void* const* d_in, const int* in_sizes, int n_in,
                              void* d_out, int out_size) {
    const float* rw  = (const float*)d_in[0];   // rewards [T, N]
    const float* val = (const float*)d_in[1];   // values  [T+1, N]
    const int*   dn  = (const int*)d_in[2];     // dones   [T, N]
    float* out = (float*)d_out;                 // [adv_norm TN | returns TN]

    int TN = in_sizes[0];
    int N  = in_sizes[1] - in_sizes[0];
    int T  = TN / N;
    int L  = T / CHUNKS;

    int groups  = N >> 2;
    int blocks1 = (CHUNKS * groups + TPB - 1) / TPB;   // 512
    int blocks2 = (N + TPB - 1) / TPB;                 // 32

    float* adv = out;
    float* ret = out + (size_t)TN;

    gae_phase1<<<blocks1, TPB>>>(rw, val, dn, N, L);
    gae_phase2<<<blocks2, TPB>>>(N, (long long)TN);
    gae_write<<<blocks1, TPB>>>(rw, val, dn, adv, ret, N, L);
}

// round 15
// speedup vs baseline: 1.2488x; 1.0870x over previous
#include <cuda_runtime.h>
#include <math.h>

#define GAMMA 0.99f
#define LAM   0.95f
#define GL    (GAMMA * LAM)
#define EPSN  1e-8

#define CHUNKS 64
#define MAXN   8192
#define TPB    256
#define P2COLS 16
#define P2BLK  (MAXN / P2COLS)   // 512 partial slots

// Static device scratch (no allocations). Zero-initialized.
__device__ float4   g_P[CHUNKS * MAXN];   // {C, D, S1, SC}    8 MB
__device__ float4   g_Q[CHUNKS * MAXN];   // {S2, SDC, SC2,_}  8 MB
__device__ float    g_carry[CHUNKS * MAXN];
__device__ double   g_part[2 * P2BLK];
__device__ unsigned g_ctr;                // last-block counter (self-resets)
__device__ float    g_mean;
__device__ float    g_inv;                // 1 / (std + eps)

// ---------------------------------------------------------------------------
// Phase 1: verbatim R2 (measured 38.5us). Per (chunk, 4-col) thread: compose
// reverse recurrence into a_out = D + C*a_in + sufficient statistics.
// ---------------------------------------------------------------------------
__global__ __launch_bounds__(TPB)
void gae_phase1(const float* __restrict__ rw, const float* __restrict__ val,
                const int* __restrict__ dn, int N, int L) {
    int groups = N >> 2;
    int tid = blockIdx.x * blockDim.x + threadIdx.x;
    if (tid >= CHUNKS * groups) return;
    int c   = tid / groups;
    int g   = tid - c * groups;
    int col = g << 2;
    int t0  = c * L;
    int t1  = t0 + L - 1;

    float C[4]  = {1.f, 1.f, 1.f, 1.f};
    float D[4]  = {0.f, 0.f, 0.f, 0.f};
    float S1[4] = {0.f, 0.f, 0.f, 0.f};
    float SC[4] = {0.f, 0.f, 0.f, 0.f};
    float S2[4] = {0.f, 0.f, 0.f, 0.f};
    float SDC[4]= {0.f, 0.f, 0.f, 0.f};
    float SC2[4]= {0.f, 0.f, 0.f, 0.f};

    float4 vn = *reinterpret_cast<const float4*>(val + (size_t)(t1 + 1) * N + col);
    #pragma unroll 4
    for (int t = t1; t >= t0; --t) {
        float4 r  = *reinterpret_cast<const float4*>(rw + (size_t)t * N + col);
        int4   dd = *reinterpret_cast<const int4*>(dn + (size_t)t * N + col);
        float4 vc = *reinterpret_cast<const float4*>(val + (size_t)t * N + col);

        float rr[4] = {r.x, r.y, r.z, r.w};
        float vv[4] = {vc.x, vc.y, vc.z, vc.w};
        float vnn[4]= {vn.x, vn.y, vn.z, vn.w};
        int   di[4] = {dd.x, dd.y, dd.z, dd.w};

        #pragma unroll
        for (int j = 0; j < 4; ++j) {
            float nt  = di[j] ? 0.f : 1.f;
            float del = fmaf(GAMMA * nt, vnn[j], rr[j]) - vv[j];
            float cf  = GL * nt;
            D[j] = fmaf(cf, D[j], del);
            C[j] *= cf;
            S1[j] += D[j];
            SC[j] += C[j];
            S2[j]  = fmaf(D[j], D[j], S2[j]);
            SDC[j] = fmaf(D[j], C[j], SDC[j]);
            SC2[j] = fmaf(C[j], C[j], SC2[j]);
        }
        vn = vc;
    }
    size_t o = (size_t)c * N + col;
    #pragma unroll
    for (int j = 0; j < 4; ++j) {
        g_P[o + j] = make_float4(C[j], D[j], S1[j], SC[j]);
        g_Q[o + j] = make_float4(S2[j], SDC[j], SC2[j], 0.f);
    }
}

// ---------------------------------------------------------------------------
// Phase 2 (tiled SMEM + fused finalize): 512 blocks x 16 columns.
//  1) cooperative coalesced load of the 64x16 tile of g_P/g_Q into SMEM
//  2) threads 0..15: 64-step serial carry scan per column, entirely in SMEM
//  3) all 256 threads: closed-form sum/sumsq from SMEM + carry; store carries
//  4) block reduce (double) -> fixed partial slot; last-arriving block reduces
//     all 512 slots in fixed order -> mean, 1/(std+eps) (ddof=1); resets ctr.
// ---------------------------------------------------------------------------
__global__ __launch_bounds__(TPB)
void gae_phase2(int N, long long M) {
    const unsigned nb = gridDim.x;
    const int colbase = blockIdx.x * P2COLS;

    __shared__ float4 sP[CHUNKS][P2COLS];   // 16 KB
    __shared__ float4 sQ[CHUNKS][P2COLS];   // 16 KB
    __shared__ float  sA[CHUNKS][P2COLS];   //  4 KB carries
    __shared__ double ss[TPB];
    __shared__ double ss2[TPB];

    // 1) coalesced tile load
    #pragma unroll 2
    for (int k = threadIdx.x; k < CHUNKS * P2COLS; k += TPB) {
        int cc = k / P2COLS, j = k - cc * P2COLS;
        size_t o = (size_t)cc * N + colbase + j;
        sP[cc][j] = g_P[o];
        sQ[cc][j] = g_Q[o];
    }
    __syncthreads();

    // 2) serial scan per column in SMEM
    if (threadIdx.x < P2COLS) {
        int j = threadIdx.x;
        float a = 0.f;
        #pragma unroll 8
        for (int cc = CHUNKS - 1; cc >= 0; --cc) {
            sA[cc][j] = a;
            float4 P = sP[cc][j];
            a = fmaf(P.x, a, P.y);
        }
    }
    __syncthreads();

    // 3) stats + carry store
    float ts = 0.f, ts2 = 0.f;
    #pragma unroll 2
    for (int k = threadIdx.x; k < CHUNKS * P2COLS; k += TPB) {
        int cc = k / P2COLS, j = k - cc * P2COLS;
        float  a = sA[cc][j];
        float4 P = sP[cc][j];
        float4 Q = sQ[cc][j];
        ts  += fmaf(P.w, a, P.z);
        ts2 += fmaf(fmaf(Q.z, a, 2.f * Q.y), a, Q.x);
        g_carry[(size_t)cc * N + colbase + j] = a;
    }

    // 4) block reduce + fused last-block finalize
    ss[threadIdx.x]  = (double)ts;
    ss2[threadIdx.x] = (double)ts2;
    __syncthreads();
    for (int st = TPB / 2; st > 0; st >>= 1) {
        if (threadIdx.x < st) {
            ss[threadIdx.x]  += ss[threadIdx.x + st];
            ss2[threadIdx.x] += ss2[threadIdx.x + st];
        }
        __syncthreads();
    }
    __shared__ bool s_last;
    if (threadIdx.x == 0) {
        g_part[2 * blockIdx.x]     = ss[0];
        g_part[2 * blockIdx.x + 1] = ss2[0];
        __threadfence();
        unsigned old = atomicAdd(&g_ctr, 1u);
        s_last = (old == nb - 1u);
    }
    __syncthreads();
    if (!s_last) return;

    double s = 0.0, s2 = 0.0;
    for (int i = threadIdx.x; i < (int)nb; i += TPB) {
        s  += g_part[2 * i];
        s2 += g_part[2 * i + 1];
    }
    ss[threadIdx.x]  = s;
    ss2[threadIdx.x] = s2;
    __syncthreads();
    for (int st = TPB / 2; st > 0; st >>= 1) {
        if (threadIdx.x < st) {
            ss[threadIdx.x]  += ss[threadIdx.x + st];
            ss2[threadIdx.x] += ss2[threadIdx.x + st];
        }
        __syncthreads();
    }
    if (threadIdx.x == 0) {
        double mean = ss[0] / (double)M;
        double var  = (ss2[0] - ss[0] * ss[0] / (double)M) / (double)(M - 1);
        if (var < 0.0) var = 0.0;
        g_mean = (float)mean;
        g_inv  = (float)(1.0 / (sqrt(var) + EPSN));
        g_ctr  = 0u;                       // reset for next graph replay
        __threadfence();
    }
}

// ---------------------------------------------------------------------------
// Write pass: untouched (measured ~50us / 75% DRAM).
// ---------------------------------------------------------------------------
__global__ __launch_bounds__(TPB)
void gae_write(const float* __restrict__ rw, const float* __restrict__ val,
               const int* __restrict__ dn, float* __restrict__ adv,
               float* __restrict__ ret, int N, int L) {
    int groups = N >> 2;
    int tid = blockIdx.x * blockDim.x + threadIdx.x;
    if (tid >= CHUNKS * groups) return;
    int c   = tid / groups;
    int g   = tid - c * groups;
    int col = g << 2;
    int t0  = c * L;
    int t1  = t0 + L - 1;

    float m   = g_mean;
    float inv = g_inv;

    float4 a  = *reinterpret_cast<const float4*>(g_carry + (size_t)c * N + col);
    float4 vn = *reinterpret_cast<const float4*>(val + (size_t)(t1 + 1) * N + col);

    #pragma unroll 4
    for (int t = t1; t >= t0; --t) {
        float4 r  = *reinterpret_cast<const float4*>(rw + (size_t)t * N + col);
        int4   dd = *reinterpret_cast<const int4*>(dn + (size_t)t * N + col);
        float4 vc = *reinterpret_cast<const float4*>(val + (size_t)t * N + col);

        float nt, del;
        nt = dd.x ? 0.f : 1.f; del = fmaf(GAMMA * nt, vn.x, r.x) - vc.x;
        a.x = fmaf(GL * nt, a.x, del);
        nt = dd.y ? 0.f : 1.f; del = fmaf(GAMMA * nt, vn.y, r.y) - vc.y;
        a.y = fmaf(GL * nt, a.y, del);
        nt = dd.z ? 0.f : 1.f; del = fmaf(GAMMA * nt, vn.z, r.z) - vc.z;
        a.z = fmaf(GL * nt, a.z, del);
        nt = dd.w ? 0.f : 1.f; del = fmaf(GAMMA * nt, vn.w, r.w) - vc.w;
        a.w = fmaf(GL * nt, a.w, del);

        size_t o = (size_t)t * N + col;
        *reinterpret_cast<float4*>(adv + o) =
            make_float4((a.x - m) * inv, (a.y - m) * inv,
                        (a.z - m) * inv, (a.w - m) * inv);
        *reinterpret_cast<float4*>(ret + o) =
            make_float4(a.x + vc.x, a.y + vc.y, a.z + vc.z, a.w + vc.w);

        vn = vc;
    }
}

extern "C" void kernel_launch(void* const* d_in, const int* in_sizes, int n_in,
                              void* d_out, int out_size) {
    const float* rw  = (const float*)d_in[0];   // rewards [T, N]
    const float* val = (const float*)d_in[1];   // values  [T+1, N]
    const int*   dn  = (const int*)d_in[2];     // dones   [T, N]
    float* out = (float*)d_out;                 // [adv_norm TN | returns TN]

    int TN = in_sizes[0];
    int N  = in_sizes[1] - in_sizes[0];
    int T  = TN / N;
    int L  = T / CHUNKS;

    int groups  = N >> 2;
    int blocks1 = (CHUNKS * groups + TPB - 1) / TPB;   // 512
    int blocks2 = N / P2COLS;                          // 512

    float* adv = out;
    float* ret = out + (size_t)TN;

    gae_phase1<<<blocks1, TPB>>>(rw, val, dn, N, L);
    gae_phase2<<<blocks2, TPB>>>(N, (long long)TN);
    gae_write<<<blocks1, TPB>>>(rw, val, dn, adv, ret, N, L);
}

// round 16
// speedup vs baseline: 1.2536x; 1.0038x over previous
#include <cuda_runtime.h>
#include <math.h>

#define GAMMA 0.99f
#define LAM   0.95f
#define GL    (GAMMA * LAM)
#define EPSN  1e-8

#define CHUNKS 64
#define MAXN   8192
#define TPB    256
#define P2COLS 16
#define P2BLK  (MAXN / P2COLS)   // 512 partial slots

// Static device scratch (no allocations). Zero-initialized.
__device__ float4   g_P[CHUNKS * MAXN];   // {C, D, S1, SC}    8 MB
__device__ float4   g_Q[CHUNKS * MAXN];   // {S2, SDC, SC2,_}  8 MB
__device__ float    g_carry[CHUNKS * MAXN];
__device__ double   g_part[2 * P2BLK];
__device__ unsigned g_ctr;                // last-block counter (self-resets)
__device__ float    g_mean;
__device__ float    g_inv;                // 1 / (std + eps)

// ---------------------------------------------------------------------------
// Phase 1: verbatim R2 (measured 38.5us). Per (chunk, 4-col) thread: compose
// reverse recurrence into a_out = D + C*a_in + sufficient statistics.
// ---------------------------------------------------------------------------
__global__ __launch_bounds__(TPB)
void gae_phase1(const float* __restrict__ rw, const float* __restrict__ val,
                const int* __restrict__ dn, int N, int L) {
    int groups = N >> 2;
    int tid = blockIdx.x * blockDim.x + threadIdx.x;
    if (tid >= CHUNKS * groups) return;
    int c   = tid / groups;
    int g   = tid - c * groups;
    int col = g << 2;
    int t0  = c * L;
    int t1  = t0 + L - 1;

    float C[4]  = {1.f, 1.f, 1.f, 1.f};
    float D[4]  = {0.f, 0.f, 0.f, 0.f};
    float S1[4] = {0.f, 0.f, 0.f, 0.f};
    float SC[4] = {0.f, 0.f, 0.f, 0.f};
    float S2[4] = {0.f, 0.f, 0.f, 0.f};
    float SDC[4]= {0.f, 0.f, 0.f, 0.f};
    float SC2[4]= {0.f, 0.f, 0.f, 0.f};

    float4 vn = *reinterpret_cast<const float4*>(val + (size_t)(t1 + 1) * N + col);
    #pragma unroll 4
    for (int t = t1; t >= t0; --t) {
        float4 r  = *reinterpret_cast<const float4*>(rw + (size_t)t * N + col);
        int4   dd = *reinterpret_cast<const int4*>(dn + (size_t)t * N + col);
        float4 vc = *reinterpret_cast<const float4*>(val + (size_t)t * N + col);

        float rr[4] = {r.x, r.y, r.z, r.w};
        float vv[4] = {vc.x, vc.y, vc.z, vc.w};
        float vnn[4]= {vn.x, vn.y, vn.z, vn.w};
        int   di[4] = {dd.x, dd.y, dd.z, dd.w};

        #pragma unroll
        for (int j = 0; j < 4; ++j) {
            float nt  = di[j] ? 0.f : 1.f;
            float del = fmaf(GAMMA * nt, vnn[j], rr[j]) - vv[j];
            float cf  = GL * nt;
            D[j] = fmaf(cf, D[j], del);
            C[j] *= cf;
            S1[j] += D[j];
            SC[j] += C[j];
            S2[j]  = fmaf(D[j], D[j], S2[j]);
            SDC[j] = fmaf(D[j], C[j], SDC[j]);
            SC2[j] = fmaf(C[j], C[j], SC2[j]);
        }
        vn = vc;
    }
    size_t o = (size_t)c * N + col;
    #pragma unroll
    for (int j = 0; j < 4; ++j) {
        g_P[o + j] = make_float4(C[j], D[j], S1[j], SC[j]);
        g_Q[o + j] = make_float4(S2[j], SDC[j], SC2[j], 0.f);
    }
}

// ---------------------------------------------------------------------------
// Phase 2 (tiled SMEM + fused finalize): 512 blocks x 16 columns.
//  1) cooperative coalesced load of the 64x16 tile of g_P/g_Q into SMEM
//  2) threads 0..15: 64-step serial carry scan per column, entirely in SMEM
//  3) all 256 threads: closed-form sum/sumsq from SMEM + carry; store carries
//  4) block reduce (double) -> fixed partial slot; last-arriving block reduces
//     all 512 slots in fixed order -> mean, 1/(std+eps) (ddof=1); resets ctr.
// ---------------------------------------------------------------------------
__global__ __launch_bounds__(TPB)
void gae_phase2(int N, long long M) {
    const unsigned nb = gridDim.x;
    const int colbase = blockIdx.x * P2COLS;

    __shared__ float4 sP[CHUNKS][P2COLS];   // 16 KB
    __shared__ float4 sQ[CHUNKS][P2COLS];   // 16 KB
    __shared__ float  sA[CHUNKS][P2COLS];   //  4 KB carries
    __shared__ double ss[TPB];
    __shared__ double ss2[TPB];

    // 1) coalesced tile load
    #pragma unroll 2
    for (int k = threadIdx.x; k < CHUNKS * P2COLS; k += TPB) {
        int cc = k / P2COLS, j = k - cc * P2COLS;
        size_t o = (size_t)cc * N + colbase + j;
        sP[cc][j] = g_P[o];
        sQ[cc][j] = g_Q[o];
    }
    __syncthreads();

    // 2) serial scan per column in SMEM
    if (threadIdx.x < P2COLS) {
        int j = threadIdx.x;
        float a = 0.f;
        #pragma unroll 8
        for (int cc = CHUNKS - 1; cc >= 0; --cc) {
            sA[cc][j] = a;
            float4 P = sP[cc][j];
            a = fmaf(P.x, a, P.y);
        }
    }
    __syncthreads();

    // 3) stats + carry store
    float ts = 0.f, ts2 = 0.f;
    #pragma unroll 2
    for (int k = threadIdx.x; k < CHUNKS * P2COLS; k += TPB) {
        int cc = k / P2COLS, j = k - cc * P2COLS;
        float  a = sA[cc][j];
        float4 P = sP[cc][j];
        float4 Q = sQ[cc][j];
        ts  += fmaf(P.w, a, P.z);
        ts2 += fmaf(fmaf(Q.z, a, 2.f * Q.y), a, Q.x);
        g_carry[(size_t)cc * N + colbase + j] = a;
    }

    // 4) block reduce + fused last-block finalize
    ss[threadIdx.x]  = (double)ts;
    ss2[threadIdx.x] = (double)ts2;
    __syncthreads();
    for (int st = TPB / 2; st > 0; st >>= 1) {
        if (threadIdx.x < st) {
            ss[threadIdx.x]  += ss[threadIdx.x + st];
            ss2[threadIdx.x] += ss2[threadIdx.x + st];
        }
        __syncthreads();
    }
    __shared__ bool s_last;
    if (threadIdx.x == 0) {
        g_part[2 * blockIdx.x]     = ss[0];
        g_part[2 * blockIdx.x + 1] = ss2[0];
        __threadfence();
        unsigned old = atomicAdd(&g_ctr, 1u);
        s_last = (old == nb - 1u);
    }
    __syncthreads();
    if (!s_last) return;

    double s = 0.0, s2 = 0.0;
    for (int i = threadIdx.x; i < (int)nb; i += TPB) {
        s  += g_part[2 * i];
        s2 += g_part[2 * i + 1];
    }
    ss[threadIdx.x]  = s;
    ss2[threadIdx.x] = s2;
    __syncthreads();
    for (int st = TPB / 2; st > 0; st >>= 1) {
        if (threadIdx.x < st) {
            ss[threadIdx.x]  += ss[threadIdx.x + st];
            ss2[threadIdx.x] += ss2[threadIdx.x + st];
        }
        __syncthreads();
    }
    if (threadIdx.x == 0) {
        double mean = ss[0] / (double)M;
        double var  = (ss2[0] - ss[0] * ss[0] / (double)M) / (double)(M - 1);
        if (var < 0.0) var = 0.0;
        g_mean = (float)mean;
        g_inv  = (float)(1.0 / (sqrt(var) + EPSN));
        g_ctr  = 0u;                       // reset for next graph replay
        __threadfence();
    }
}

// ---------------------------------------------------------------------------
// Write pass: untouched (measured ~50us / 75% DRAM).
// ---------------------------------------------------------------------------
__global__ __launch_bounds__(TPB)
void gae_write(const float* __restrict__ rw, const float* __restrict__ val,
               const int* __restrict__ dn, float* __restrict__ adv,
               float* __restrict__ ret, int N, int L) {
    int groups = N >> 2;
    int tid = blockIdx.x * blockDim.x + threadIdx.x;
    if (tid >= CHUNKS * groups) return;
    int c   = tid / groups;
    int g   = tid - c * groups;
    int col = g << 2;
    int t0  = c * L;
    int t1  = t0 + L - 1;

    float m   = g_mean;
    float inv = g_inv;

    float4 a  = *reinterpret_cast<const float4*>(g_carry + (size_t)c * N + col);
    float4 vn = *reinterpret_cast<const float4*>(val + (size_t)(t1 + 1) * N + col);

    #pragma unroll 4
    for (int t = t1; t >= t0; --t) {
        float4 r  = *reinterpret_cast<const float4*>(rw + (size_t)t * N + col);
        int4   dd = *reinterpret_cast<const int4*>(dn + (size_t)t * N + col);
        float4 vc = *reinterpret_cast<const float4*>(val + (size_t)t * N + col);

        float nt, del;
        nt = dd.x ? 0.f : 1.f; del = fmaf(GAMMA * nt, vn.x, r.x) - vc.x;
        a.x = fmaf(GL * nt, a.x, del);
        nt = dd.y ? 0.f : 1.f; del = fmaf(GAMMA * nt, vn.y, r.y) - vc.y;
        a.y = fmaf(GL * nt, a.y, del);
        nt = dd.z ? 0.f : 1.f; del = fmaf(GAMMA * nt, vn.z, r.z) - vc.z;
        a.z = fmaf(GL * nt, a.z, del);
        nt = dd.w ? 0.f : 1.f; del = fmaf(GAMMA * nt, vn.w, r.w) - vc.w;
        a.w = fmaf(GL * nt, a.w, del);

        size_t o = (size_t)t * N + col;
        *reinterpret_cast<float4*>(adv + o) =
            make_float4((a.x - m) * inv, (a.y - m) * inv,
                        (a.z - m) * inv, (a.w - m) * inv);
        *reinterpret_cast<float4*>(ret + o) =
            make_float4(a.x + vc.x, a.y + vc.y, a.z + vc.z, a.w + vc.w);

        vn = vc;
    }
}

extern "C" void kernel_launch(void* const* d_in, const int* in_sizes, int n_in,
                              void* d_out, int out_size) {
    const float* rw  = (const float*)d_in[0];   // rewards [T, N]
    const float* val = (const float*)d_in[1];   // values  [T+1, N]
    const int*   dn  = (const int*)d_in[2];     // dones   [T, N]
    float* out = (float*)d_out;                 // [adv_norm TN | returns TN]

    int TN = in_sizes[0];
    int N  = in_sizes[1] - in_sizes[0];
    int T  = TN / N;
    int L  = T / CHUNKS;

    int groups  = N >> 2;
    int blocks1 = (CHUNKS * groups + TPB - 1) / TPB;   // 512
    int blocks2 = N / P2COLS;                          // 512

    float* adv = out;
    float* ret = out + (size_t)TN;

    gae_phase1<<<blocks1, TPB>>>(rw, val, dn, N, L);
    gae_phase2<<<blocks2, TPB>>>(N, (long long)TN);
    gae_write<<<blocks1, TPB>>>(rw, val, dn, adv, ret, N, L);
}